// round 2
// baseline (speedup 1.0000x reference)
#include <cuda_runtime.h>
#include <cstdint>

// Problem constants
#define BATCH 64
#define SEQT  512
#define IN    512
#define HID   1024
#define G4    4096      // 4*HID
#define KTOT  1536      // IN + HID
#define OUTD  512

#define NBLK  128       // persistent grid size (all co-resident, 1 CTA/SM)
#define NTHR  256

// ---- device-global scratch (no allocation allowed) ----
__device__ float    d_W[(size_t)G4 * KTOT];   // packed [Wx|Wh] per gate row, 25 MB (L2-resident)
__device__ float    d_bias[G4];
__device__ float    d_h[BATCH * HID];
__device__ float    d_c[BATCH * HID];
__device__ float    d_g[BATCH * G4];          // per-step gate pre-activations
__device__ unsigned d_bar;                    // grid barrier counter

// ============================================================================
// Prep: pack weights/biases, zero state, reset barrier. Runs every replay.
// ============================================================================
__global__ void prep_kernel(
    const float* __restrict__ Wxf, const float* __restrict__ Whf, const float* __restrict__ bhf,
    const float* __restrict__ Wxi, const float* __restrict__ Whi, const float* __restrict__ bhi,
    const float* __restrict__ Wxc, const float* __restrict__ Whc, const float* __restrict__ bhc,
    const float* __restrict__ Wxo, const float* __restrict__ Who, const float* __restrict__ bho)
{
    const float* Wx[4] = {Wxf, Wxi, Wxc, Wxo};
    const float* Wh[4] = {Whf, Whi, Whc, Who};
    const float* bh[4] = {bhf, bhi, bhc, bho};

    size_t gid    = (size_t)blockIdx.x * blockDim.x + threadIdx.x;
    size_t stride = (size_t)gridDim.x * blockDim.x;

    for (size_t i = gid; i < (size_t)G4 * KTOT; i += stride) {
        int j = (int)(i / KTOT);
        int k = (int)(i % KTOT);
        int g = j >> 10;            // gate 0..3 (f,i,c,o)
        int r = j & (HID - 1);      // hidden row
        d_W[i] = (k < IN) ? Wx[g][(size_t)r * IN + k]
                          : Wh[g][(size_t)r * HID + (k - IN)];
    }
    for (size_t i = gid; i < (size_t)G4; i += stride) {
        int g = (int)(i >> 10), r = (int)(i & (HID - 1));
        d_bias[i] = bh[g][r];
    }
    for (size_t i = gid; i < (size_t)BATCH * HID; i += stride) {
        d_h[i] = 0.f;
        d_c[i] = 0.f;
    }
    if (gid == 0) d_bar = 0u;
}

// ============================================================================
// Grid barrier: all NBLK CTAs are co-resident (1 CTA/SM). Counter-based,
// monotone target per epoch; deterministic.
// ============================================================================
__device__ __forceinline__ void grid_bar(unsigned target)
{
    __syncthreads();
    if (threadIdx.x == 0) {
        __threadfence();                       // release my writes
        atomicAdd(&d_bar, 1u);
        while (*(volatile unsigned*)&d_bar < target) __nanosleep(64);
        __threadfence();                       // acquire peers' writes
    }
    __syncthreads();
}

__device__ __forceinline__ float sigf(float v)  { return 1.f / (1.f + __expf(-v)); }
__device__ __forceinline__ float tanhfast(float v) { return 2.f / (1.f + __expf(-2.f * v)) - 1.f; }

// ============================================================================
// Persistent LSTM kernel.
// Phase 1 (per step): g[64x4096] = [x_t | h] @ W^T + b   (block tile 64x32,
//   thread tile 2x4, K streamed in 32-chunks through smem)
// Phase 2 (per step): elementwise gate update of c, h.
// Tail: out = h_T @ Wout^T + bout.
// ============================================================================
__global__ void __launch_bounds__(NTHR, 1) lstm_kernel(
    const float* __restrict__ x,
    const float* __restrict__ Wout,
    const float* __restrict__ bout,
    float* __restrict__ out)
{
    __shared__ float Vs[32 * 65];   // [kk][b], padded to 65 (bank-conflict-free)
    __shared__ float Ws[32 * 36];   // [kk][n], padded to 36 (16B-aligned float4 rows)

    const int tid  = threadIdx.x;
    const int tm   = tid & 31;        // batch-row pair selector (rows tm, tm+32)
    const int tn   = tid >> 5;        // 0..7, 4 output cols each
    const int n0   = blockIdx.x * 32; // this block's gate-column range
    const int gtid = blockIdx.x * NTHR + tid;
    unsigned ep = 0;

    float bias[4];
#pragma unroll
    for (int c = 0; c < 4; c++) bias[c] = d_bias[n0 + tn * 4 + c];

    for (int t = 0; t < SEQT; t++) {
        float acc0[4], acc1[4];
#pragma unroll
        for (int c = 0; c < 4; c++) { acc0[c] = bias[c]; acc1[c] = bias[c]; }

        // ---- Phase 1a: x-part (K = 0..511) ----
        for (int kb = 0; kb < IN; kb += 32) {
#pragma unroll
            for (int i = tid; i < 64 * 32; i += NTHR) {
                int b = i >> 5, kk = i & 31;
                Vs[kk * 65 + b] =
                    __ldg(&x[((size_t)b << 18) + ((size_t)t << 9) + kb + kk]);
            }
#pragma unroll
            for (int i = tid; i < 32 * 32; i += NTHR) {
                int n = i >> 5, kk = i & 31;
                Ws[kk * 36 + n] = d_W[(size_t)(n0 + n) * KTOT + kb + kk];
            }
            __syncthreads();
#pragma unroll
            for (int k = 0; k < 32; k++) {
                float a0 = Vs[k * 65 + tm];
                float a1 = Vs[k * 65 + 32 + tm];
                float4 w = *(const float4*)&Ws[k * 36 + tn * 4];
                acc0[0] += a0 * w.x; acc0[1] += a0 * w.y;
                acc0[2] += a0 * w.z; acc0[3] += a0 * w.w;
                acc1[0] += a1 * w.x; acc1[1] += a1 * w.y;
                acc1[2] += a1 * w.z; acc1[3] += a1 * w.w;
            }
            __syncthreads();
        }

        // ---- Phase 1b: h-part (K = 512..1535) ----
        for (int kb = 0; kb < HID; kb += 32) {
#pragma unroll
            for (int i = tid; i < 64 * 32; i += NTHR) {
                int b = i >> 5, kk = i & 31;
                Vs[kk * 65 + b] = __ldcg(&d_h[(b << 10) + kb + kk]);
            }
#pragma unroll
            for (int i = tid; i < 32 * 32; i += NTHR) {
                int n = i >> 5, kk = i & 31;
                Ws[kk * 36 + n] = d_W[(size_t)(n0 + n) * KTOT + IN + kb + kk];
            }
            __syncthreads();
#pragma unroll
            for (int k = 0; k < 32; k++) {
                float a0 = Vs[k * 65 + tm];
                float a1 = Vs[k * 65 + 32 + tm];
                float4 w = *(const float4*)&Ws[k * 36 + tn * 4];
                acc0[0] += a0 * w.x; acc0[1] += a0 * w.y;
                acc0[2] += a0 * w.z; acc0[3] += a0 * w.w;
                acc1[0] += a1 * w.x; acc1[1] += a1 * w.y;
                acc1[2] += a1 * w.z; acc1[3] += a1 * w.w;
            }
            __syncthreads();
        }

        // store gate pre-activations
#pragma unroll
        for (int c = 0; c < 4; c++) {
            __stcg(&d_g[((size_t)tm << 12) + n0 + tn * 4 + c],        acc0[c]);
            __stcg(&d_g[((size_t)(tm + 32) << 12) + n0 + tn * 4 + c], acc1[c]);
        }

        grid_bar((++ep) * NBLK);

        // ---- Phase 2: gate update (each global thread owns fixed (b,r)) ----
#pragma unroll
        for (int idx = gtid; idx < BATCH * HID; idx += NBLK * NTHR) {
            int b = idx >> 10, r = idx & (HID - 1);
            const float* gr = d_g + ((size_t)b << 12);
            float f  = sigf(__ldcg(gr + r));
            float ig = sigf(__ldcg(gr + HID + r));
            float cc = tanhfast(__ldcg(gr + 2 * HID + r));
            float o  = sigf(__ldcg(gr + 3 * HID + r));
            float c  = f * d_c[idx] + ig * cc;
            d_c[idx] = c;
            __stcg(&d_h[idx], o * tanhfast(c));
        }

        grid_bar((++ep) * NBLK);
    }

    // ---- Tail: out[b][o] = h_T[b] . Wout[o] + bout[o]  (32768 outs, 1/thread)
    for (int idx = gtid; idx < BATCH * OUTD; idx += NBLK * NTHR) {
        int b = idx >> 9, o = idx & (OUTD - 1);
        const float4* hr = (const float4*)(d_h + ((size_t)b << 10));
        const float4* wr = (const float4*)(Wout + ((size_t)o << 10));
        float s = bout[o];
#pragma unroll 4
        for (int k = 0; k < HID / 4; k++) {
            float4 h4 = __ldcg(hr + k);
            float4 w4 = __ldg(wr + k);
            s += h4.x * w4.x + h4.y * w4.y + h4.z * w4.z + h4.w * w4.w;
        }
        out[idx] = s;
    }
}

// ============================================================================
// Launch: prep (repack + reset) then one persistent kernel. Graph-capturable.
// ============================================================================
extern "C" void kernel_launch(void* const* d_in, const int* in_sizes, int n_in,
                              void* d_out, int out_size)
{
    (void)in_sizes; (void)n_in; (void)out_size;
    const float* x    = (const float*)d_in[0];
    const float* Wxf  = (const float*)d_in[1];
    const float* Whf  = (const float*)d_in[2];
    const float* bhf  = (const float*)d_in[3];
    const float* Wxi  = (const float*)d_in[4];
    const float* Whi  = (const float*)d_in[5];
    const float* bhi  = (const float*)d_in[6];
    const float* Wxc  = (const float*)d_in[7];
    const float* Whc  = (const float*)d_in[8];
    const float* bhc  = (const float*)d_in[9];
    const float* Wxo  = (const float*)d_in[10];
    const float* Who  = (const float*)d_in[11];
    const float* bho  = (const float*)d_in[12];
    const float* Wout = (const float*)d_in[13];
    const float* bout = (const float*)d_in[14];
    float* out = (float*)d_out;

    prep_kernel<<<2048, 256>>>(Wxf, Whf, bhf, Wxi, Whi, bhi,
                               Wxc, Whc, bhc, Wxo, Who, bho);
    lstm_kernel<<<NBLK, NTHR>>>(x, Wout, bout, out);
}

// round 3
// speedup vs baseline: 2.2688x; 2.2688x over previous
#include <cuda_runtime.h>
#include <cstdint>

// Problem constants
#define BATCH 64
#define SEQT  512
#define IN    512
#define HID   1024
#define G4    4096      // 4*HID
#define KTOT  1536      // IN + HID
#define OUTD  512

#define NBLK  128       // persistent grid (all co-resident, 1 CTA/SM)
#define NTHR  256
#define NCHUNK 48       // 48 chunks of K=32 (16 x-chunks + 32 h-chunks)

// ---- device-global scratch (no allocation allowed) ----
// W packed so CTA j owns columns j*32..j*32+31 = hidden units j*8..j*8+7, each
// unit contributing its 4 gate rows [f,i,c,o], each row = [Wx | Wh] (K=1536).
__device__ float    d_W[(size_t)G4 * KTOT];   // 25 MB, L2-resident
__device__ float    d_bias[G4];
__device__ float    d_hT[2 * HID * BATCH];    // double-buffered h, TRANSPOSED [unit][batch]
__device__ unsigned d_bar;

// ============================================================================
// Prep: pack weights/biases in fused-gate order, zero h buffers, reset barrier.
// ============================================================================
__global__ void prep_kernel(
    const float* __restrict__ Wxf, const float* __restrict__ Whf, const float* __restrict__ bhf,
    const float* __restrict__ Wxi, const float* __restrict__ Whi, const float* __restrict__ bhi,
    const float* __restrict__ Wxc, const float* __restrict__ Whc, const float* __restrict__ bhc,
    const float* __restrict__ Wxo, const float* __restrict__ Who, const float* __restrict__ bho)
{
    const float* Wx[4] = {Wxf, Wxi, Wxc, Wxo};
    const float* Wh[4] = {Whf, Whi, Whc, Who};
    const float* bh[4] = {bhf, bhi, bhc, bho};

    size_t gid    = (size_t)blockIdx.x * blockDim.x + threadIdx.x;
    size_t stride = (size_t)gridDim.x * blockDim.x;

    for (size_t i = gid; i < (size_t)G4 * KTOT; i += stride) {
        int j  = (int)(i / KTOT);          // packed column 0..4095
        int k  = (int)(i % KTOT);
        int g  = j & 3;                    // gate 0..3 = f,i,c,o
        int r  = (j >> 5) * 8 + ((j >> 2) & 7);   // global hidden unit
        d_W[i] = (k < IN) ? Wx[g][(size_t)r * IN + k]
                          : Wh[g][(size_t)r * HID + (k - IN)];
    }
    for (size_t i = gid; i < (size_t)G4; i += stride) {
        int g = (int)(i & 3);
        int r = (int)((i >> 5) * 8 + ((i >> 2) & 7));
        d_bias[i] = bh[g][r];
    }
    for (size_t i = gid; i < (size_t)2 * HID * BATCH; i += stride)
        d_hT[i] = 0.f;
    if (gid == 0) d_bar = 0u;
}

// ============================================================================
// Grid barrier (128 co-resident CTAs), counter-based, monotone target.
// ============================================================================
__device__ __forceinline__ void grid_bar(unsigned target)
{
    __syncthreads();
    if (threadIdx.x == 0) {
        __threadfence();
        atomicAdd(&d_bar, 1u);
        while (*(volatile unsigned*)&d_bar < target) __nanosleep(32);
        __threadfence();
    }
    __syncthreads();
}

__device__ __forceinline__ float sigf(float v)     { return 1.f / (1.f + __expf(-v)); }
__device__ __forceinline__ float tanhfast(float v) { return 2.f / (1.f + __expf(-2.f * v)) - 1.f; }

// smem tile geometry
#define VPAD 65   // Vs row pitch  (conflict-free scalar reads)
#define WPAD 40   // Ws row pitch  (16B-aligned float4, 4-way store conflicts)

// global -> registers (prefetch) for chunk q of step t
__device__ __forceinline__ void ld_chunk(
    int q, int t, int rbuf, int n0, int tid,
    const float* __restrict__ x, float pv[8], float pw[4])
{
    const int kb = q << 5;
    if (q < 16) {           // x part: K = 0..511
#pragma unroll
        for (int j = 0; j < 8; j++) {
            int i = tid + j * NTHR;
            int b = i >> 5, kk = i & 31;
            pv[j] = __ldg(&x[((size_t)b << 18) + ((size_t)t << 9) + kb + kk]);
        }
    } else {                // h part: K = 512..1535, transposed [unit][batch]
        const float* hb = d_hT + (size_t)rbuf * HID * BATCH + ((size_t)(kb - IN) << 6);
#pragma unroll
        for (int j = 0; j < 8; j++) {
            int i = tid + j * NTHR;
            int kk = i >> 6, b = i & 63;
            pv[j] = __ldcg(&hb[(kk << 6) + b]);
        }
    }
#pragma unroll
    for (int j = 0; j < 4; j++) {
        int i = tid + j * NTHR;
        int n = i >> 5, kk = i & 31;
        pw[j] = __ldg(&d_W[(size_t)(n0 + n) * KTOT + kb + kk]);
    }
}

// registers -> smem for chunk q
__device__ __forceinline__ void st_chunk(
    int q, int tid, float* __restrict__ Vs, float* __restrict__ Ws,
    const float pv[8], const float pw[4])
{
    if (q < 16) {
#pragma unroll
        for (int j = 0; j < 8; j++) {
            int i = tid + j * NTHR;
            int b = i >> 5, kk = i & 31;
            Vs[kk * VPAD + b] = pv[j];
        }
    } else {
#pragma unroll
        for (int j = 0; j < 8; j++) {
            int i = tid + j * NTHR;
            int kk = i >> 6, b = i & 63;
            Vs[kk * VPAD + b] = pv[j];
        }
    }
#pragma unroll
    for (int j = 0; j < 4; j++) {
        int i = tid + j * NTHR;
        int n = i >> 5, kk = i & 31;
        Ws[kk * WPAD + n] = pw[j];
    }
}

// ============================================================================
// Persistent fused LSTM kernel.
// Per step: g = [x_t | h] @ W^T + b   (block tile 64 batch x 32 cols, software
// pipelined, 1 syncthreads/chunk), then in-register gate math (c stays in
// registers), coalesced transposed h write, ONE grid barrier per step.
// ============================================================================
__global__ void __launch_bounds__(NTHR, 1) lstm_kernel(
    const float* __restrict__ x,
    const float* __restrict__ Wout,
    const float* __restrict__ bout,
    float* __restrict__ out)
{
    __shared__ float Vs[2][32 * VPAD];
    __shared__ float Ws[2][32 * WPAD];

    const int tid  = threadIdx.x;
    const int tm   = tid & 31;          // batch rows tm, tm+32
    const int tn   = tid >> 5;          // local unit 0..7
    const int n0   = blockIdx.x << 5;   // packed column base
    const int unit = (blockIdx.x << 3) + tn;   // global hidden unit
    const int gtid = blockIdx.x * NTHR + tid;

    float bias[4];
#pragma unroll
    for (int c = 0; c < 4; c++) bias[c] = d_bias[n0 + (tn << 2) + c];

    float cst0 = 0.f, cst1 = 0.f;       // cell state in registers

    for (int t = 0; t < SEQT; t++) {
        const int rbuf = t & 1;         // read h(t-1) from this buffer
        const int wbuf = rbuf ^ 1;      // write h(t) to this buffer

        float acc0[4], acc1[4];
#pragma unroll
        for (int c = 0; c < 4; c++) { acc0[c] = bias[c]; acc1[c] = bias[c]; }

        float pv[8], pw[4];
        ld_chunk(0, t, rbuf, n0, tid, x, pv, pw);
        st_chunk(0, tid, Vs[0], Ws[0], pv, pw);
        __syncthreads();

#pragma unroll 2
        for (int q = 0; q < NCHUNK; q++) {
            const int cur = q & 1;
            if (q + 1 < NCHUNK)
                ld_chunk(q + 1, t, rbuf, n0, tid, x, pv, pw);

            const float* vs = Vs[cur];
            const float* ws = Ws[cur];
#pragma unroll
            for (int k = 0; k < 32; k++) {
                float a0 = vs[k * VPAD + tm];
                float a1 = vs[k * VPAD + 32 + tm];
                float4 w = *(const float4*)&ws[k * WPAD + (tn << 2)];
                acc0[0] += a0 * w.x; acc0[1] += a0 * w.y;
                acc0[2] += a0 * w.z; acc0[3] += a0 * w.w;
                acc1[0] += a1 * w.x; acc1[1] += a1 * w.y;
                acc1[2] += a1 * w.z; acc1[3] += a1 * w.w;
            }
            if (q + 1 < NCHUNK) {
                st_chunk(q + 1, tid, Vs[cur ^ 1], Ws[cur ^ 1], pv, pw);
                __syncthreads();
            }
        }

        // ---- in-register gate update ----
        {
            float f  = sigf(acc0[0]);
            float ig = sigf(acc0[1]);
            float cc = tanhfast(acc0[2]);
            float o  = sigf(acc0[3]);
            cst0 = f * cst0 + ig * cc;
            __stcg(&d_hT[(size_t)wbuf * HID * BATCH + (unit << 6) + tm],
                   o * tanhfast(cst0));
        }
        {
            float f  = sigf(acc1[0]);
            float ig = sigf(acc1[1]);
            float cc = tanhfast(acc1[2]);
            float o  = sigf(acc1[3]);
            cst1 = f * cst1 + ig * cc;
            __stcg(&d_hT[(size_t)wbuf * HID * BATCH + (unit << 6) + 32 + tm],
                   o * tanhfast(cst1));
        }

        grid_bar((unsigned)(t + 1) * NBLK);
    }

    // ---- Tail: out[b][o] = h_T[b] . Wout[o] + bout[o]
    // final h is in buffer 0 (step 511 wrote wbuf = 0). One output per thread:
    // lanes vary over batch -> coalesced hT reads, broadcast Wout reads.
    {
        const int b = gtid & 63;
        const int o = gtid >> 6;                 // 0..511
        const float* hb = d_hT;                  // buffer 0
        float s = __ldg(&bout[o]);
#pragma unroll 8
        for (int k = 0; k < HID; k++)
            s += __ldcg(&hb[(k << 6) + b]) * __ldg(&Wout[((size_t)o << 10) + k]);
        out[(size_t)b * OUTD + o] = s;
    }
}

// ============================================================================
extern "C" void kernel_launch(void* const* d_in, const int* in_sizes, int n_in,
                              void* d_out, int out_size)
{
    (void)in_sizes; (void)n_in; (void)out_size;
    const float* x    = (const float*)d_in[0];
    const float* Wxf  = (const float*)d_in[1];
    const float* Whf  = (const float*)d_in[2];
    const float* bhf  = (const float*)d_in[3];
    const float* Wxi  = (const float*)d_in[4];
    const float* Whi  = (const float*)d_in[5];
    const float* bhi  = (const float*)d_in[6];
    const float* Wxc  = (const float*)d_in[7];
    const float* Whc  = (const float*)d_in[8];
    const float* bhc  = (const float*)d_in[9];
    const float* Wxo  = (const float*)d_in[10];
    const float* Who  = (const float*)d_in[11];
    const float* bho  = (const float*)d_in[12];
    const float* Wout = (const float*)d_in[13];
    const float* bout = (const float*)d_in[14];
    float* out = (float*)d_out;

    prep_kernel<<<2048, 256>>>(Wxf, Whf, bhf, Wxi, Whi, bhi,
                               Wxc, Whc, bhc, Wxo, Who, bho);
    lstm_kernel<<<NBLK, NTHR>>>(x, Wout, bout, out);
}

// round 5
// speedup vs baseline: 2.9944x; 1.3198x over previous
#include <cuda_runtime.h>
#include <cstdint>

// Problem constants
#define BATCH 64
#define SEQT  512
#define IN    512
#define HID   1024
#define G4    4096
#define KTOT  1536
#define OUTD  512

#define NBLK  128           // persistent grid, 1 CTA/SM
#define NTHR  256           // warps 0-1 compute (mma), 2-7 staging
#define KC    64            // K per chunk
#define NCHUNK (KTOT / KC)  // 24 (8 x-chunks + 16 h-chunks)

// smem: W resident (32 rows x 1536, pitch 1540 fl) + double-buffered A chunk
#define WPITCH 1540
#define APITCH 68
#define W_BYTES  (32 * WPITCH * 4)          // 197120
#define A_BYTES  (BATCH * APITCH * 4)       // 17408
#define OFF_A    W_BYTES
#define SMEM_TOTAL (W_BYTES + 2 * A_BYTES)  // 231936 <= 232448 max

// ---- device-global scratch ----
__device__ float    d_W[(size_t)G4 * KTOT];            // tf32-rounded, packed
__device__ float    d_bias[G4];
__device__ float    d_xr[(size_t)SEQT * BATCH * IN];   // tf32-rounded, [t][b][k]
__device__ float    d_h[2][BATCH][HID];                // double-buffered h
__device__ unsigned d_bar;

// ============================ helpers =======================================
__device__ __forceinline__ float tf32r(float v) {
    uint32_t r;
    asm("cvt.rna.tf32.f32 %0, %1;" : "=r"(r) : "f"(v));
    return __uint_as_float(r);
}
__device__ __forceinline__ void mma_tf32(float c[4], const uint32_t a[4],
                                         const uint32_t b[2]) {
    asm volatile(
        "mma.sync.aligned.m16n8k8.row.col.f32.tf32.tf32.f32 "
        "{%0,%1,%2,%3}, {%4,%5,%6,%7}, {%8,%9}, {%0,%1,%2,%3};"
        : "+f"(c[0]), "+f"(c[1]), "+f"(c[2]), "+f"(c[3])
        : "r"(a[0]), "r"(a[1]), "r"(a[2]), "r"(a[3]), "r"(b[0]), "r"(b[1]));
}
__device__ __forceinline__ float sigf(float v)     { return 1.f / (1.f + __expf(-v)); }
__device__ __forceinline__ float tanhfast(float v) { return 2.f / (1.f + __expf(-2.f * v)) - 1.f; }

// ============================ prep kernel ===================================
// Packed column j: gate = (j>>3)&3 (f,i,c,o), unit = (j>>5)*8 + (j&7).
// CTA blk owns j in [blk*32, blk*32+32) = units blk*8..blk*8+7, all 4 gates.
__global__ void prep_kernel(
    const float* __restrict__ x,
    const float* __restrict__ Wxf, const float* __restrict__ Whf, const float* __restrict__ bhf,
    const float* __restrict__ Wxi, const float* __restrict__ Whi, const float* __restrict__ bhi,
    const float* __restrict__ Wxc, const float* __restrict__ Whc, const float* __restrict__ bhc,
    const float* __restrict__ Wxo, const float* __restrict__ Who, const float* __restrict__ bho)
{
    const float* Wx[4] = {Wxf, Wxi, Wxc, Wxo};
    const float* Wh[4] = {Whf, Whi, Whc, Who};
    const float* bh[4] = {bhf, bhi, bhc, bho};

    size_t gid = (size_t)blockIdx.x * blockDim.x + threadIdx.x;
    size_t str = (size_t)gridDim.x * blockDim.x;

    for (size_t i = gid; i < (size_t)G4 * KTOT; i += str) {
        int j = (int)(i / KTOT), k = (int)(i % KTOT);
        int g = (j >> 3) & 3;
        int r = (j >> 5) * 8 + (j & 7);
        float v = (k < IN) ? Wx[g][(size_t)r * IN + k]
                           : Wh[g][(size_t)r * HID + (k - IN)];
        d_W[i] = tf32r(v);
    }
    for (size_t i = gid; i < (size_t)G4; i += str) {
        int g = (int)((i >> 3) & 3);
        int r = (int)((i >> 5) * 8 + (i & 7));
        d_bias[i] = bh[g][r];
    }
    // x transposed to [t][b][k], tf32-rounded
    for (size_t i = gid; i < (size_t)SEQT * BATCH * IN; i += str) {
        int t = (int)(i / (BATCH * IN));
        int b = (int)((i / IN) % BATCH);
        int k = (int)(i % IN);
        d_xr[i] = tf32r(x[((size_t)b * SEQT + t) * IN + k]);
    }
    for (size_t i = gid; i < (size_t)2 * BATCH * HID; i += str)
        ((float*)d_h)[i] = 0.f;
    if (gid == 0) d_bar = 0u;
}

// ============================ grid barrier ==================================
__device__ __forceinline__ void grid_bar(unsigned target)
{
    __syncthreads();
    if (threadIdx.x == 0) {
        __threadfence();
        atomicAdd(&d_bar, 1u);
        while (*(volatile unsigned*)&d_bar < target) __nanosleep(32);
        __threadfence();
    }
    __syncthreads();
}

// ============================ staging (k-interleaved STS) ===================
// Interleave within each logical k8-group: slot 2q = k q, slot 2q+1 = k q+4,
// so every mma fragment (k, k+4) is one float2 in smem.
__device__ __forceinline__ void interleave_sts(float* dst, float4 va, float4 vb)
{
    ((float4*)dst)[0] = make_float4(va.x, vb.x, va.y, vb.y);
    ((float4*)dst)[1] = make_float4(va.z, vb.z, va.w, vb.w);
}

__device__ __forceinline__ void stage_chunk(float* Abuf, int t, int q, int rbuf, int stid)
{
    const int kglob0 = q * KC;
#pragma unroll
    for (int gidx = stid; gidx < 512; gidx += 192) {
        int b  = gidx >> 3;
        int kg = kglob0 + (gidx & 7) * 8;
        float4 va, vb;
        if (kg < IN) {
            const float4* p = (const float4*)&d_xr[((size_t)t * BATCH + b) * IN + kg];
            va = __ldg(p); vb = __ldg(p + 1);
        } else {
            const float4* p = (const float4*)&d_h[rbuf][b][kg - IN];
            va = __ldcg(p); vb = __ldcg(p + 1);
        }
        interleave_sts(&Abuf[b * APITCH + (gidx & 7) * 8], va, vb);
    }
}

// ============================ main persistent kernel ========================
__global__ void __launch_bounds__(NTHR, 1) lstm_kernel(
    const float* __restrict__ Wout,
    const float* __restrict__ bout,
    float* __restrict__ out)
{
    extern __shared__ char smem[];
    float* Ws = (float*)smem;
    float* As[2] = { (float*)(smem + OFF_A), (float*)(smem + OFF_A + A_BYTES) };

    const int tid  = threadIdx.x;
    const int wid  = tid >> 5;
    const int lane = tid & 31;
    const int g8   = lane >> 2;        // 0..7 group row
    const int ql   = lane & 3;         // 0..3
    const int blk  = blockIdx.x;
    const int u0   = blk * 8;          // global hidden-unit base

    // ---- one-time: load W tile (32 rows x 1536) into smem, interleaved ----
    for (int g = tid; g < 32 * 192; g += NTHR) {
        int n = g / 192, k8 = g % 192;
        const float4* p = (const float4*)&d_W[(size_t)(blk * 32 + n) * KTOT + k8 * 8];
        float4 va = __ldg(p), vb = __ldg(p + 1);
        interleave_sts(&Ws[n * WPITCH + k8 * 8], va, vb);
    }
    __syncthreads();

    const bool isCompute = (wid < 2);
    const int  stid      = tid - 64;            // staging thread id (wid>=2)
    const int  wbase     = wid * 32;            // compute warp batch-row base

    // compute-warp persistent state
    float cst[2][2][2];                         // [mt][half][e]
    float bias[4][2];                           // [gate][e]
    if (isCompute) {
#pragma unroll
        for (int a = 0; a < 2; a++)
#pragma unroll
            for (int b = 0; b < 2; b++) { cst[a][b][0] = 0.f; cst[a][b][1] = 0.f; }
#pragma unroll
        for (int nt = 0; nt < 4; nt++) {
            bias[nt][0] = __ldg(&d_bias[blk * 32 + nt * 8 + 2 * ql]);
            bias[nt][1] = __ldg(&d_bias[blk * 32 + nt * 8 + 2 * ql + 1]);
        }
    }

    for (int t = 0; t < SEQT; t++) {
        const int rbuf = t & 1, wbuf = rbuf ^ 1;

        float acc[2][4][4];
        if (isCompute) {
#pragma unroll
            for (int mt = 0; mt < 2; mt++)
#pragma unroll
                for (int nt = 0; nt < 4; nt++)
#pragma unroll
                    for (int c = 0; c < 4; c++) acc[mt][nt][c] = 0.f;
        }

        if (!isCompute) stage_chunk(As[0], t, 0, rbuf, stid);
        __syncthreads();

#pragma unroll 2
        for (int q = 0; q < NCHUNK; q++) {
            if (!isCompute) {
                if (q + 1 < NCHUNK)
                    stage_chunk(As[(q + 1) & 1], t, q + 1, rbuf, stid);
            } else {
                const float* Ab = As[q & 1];
                const float* Wb = Ws + q * KC;
#pragma unroll
                for (int kk = 0; kk < 8; kk++) {
                    uint32_t afr[2][4];
#pragma unroll
                    for (int mt = 0; mt < 2; mt++) {
                        float2 lo = *(const float2*)&Ab[(wbase + mt * 16 + g8) * APITCH + kk * 8 + 2 * ql];
                        float2 hi = *(const float2*)&Ab[(wbase + mt * 16 + 8 + g8) * APITCH + kk * 8 + 2 * ql];
                        afr[mt][0] = __float_as_uint(lo.x);
                        afr[mt][1] = __float_as_uint(hi.x);
                        afr[mt][2] = __float_as_uint(lo.y);
                        afr[mt][3] = __float_as_uint(hi.y);
                    }
                    uint32_t bfr[4][2];
#pragma unroll
                    for (int nt = 0; nt < 4; nt++) {
                        float2 bb = *(const float2*)&Wb[(nt * 8 + g8) * WPITCH + kk * 8 + 2 * ql];
                        bfr[nt][0] = __float_as_uint(bb.x);
                        bfr[nt][1] = __float_as_uint(bb.y);
                    }
#pragma unroll
                    for (int mt = 0; mt < 2; mt++)
#pragma unroll
                        for (int nt = 0; nt < 4; nt++)
                            mma_tf32(acc[mt][nt], afr[mt], bfr[nt]);
                }
            }
            __syncthreads();
        }

        // ---- epilogue: in-register gate fusion, write h(t) ----
        if (isCompute) {
#pragma unroll
            for (int mt = 0; mt < 2; mt++) {
#pragma unroll
                for (int half = 0; half < 2; half++) {
                    float hv[2];
#pragma unroll
                    for (int e = 0; e < 2; e++) {
                        const int c = half * 2 + e;
                        float f  = sigf(acc[mt][0][c] + bias[0][e]);
                        float ig = sigf(acc[mt][1][c] + bias[1][e]);
                        float ch = tanhfast(acc[mt][2][c] + bias[2][e]);
                        float o  = sigf(acc[mt][3][c] + bias[3][e]);
                        float cs = f * cst[mt][half][e] + ig * ch;
                        cst[mt][half][e] = cs;
                        hv[e] = tf32r(o * tanhfast(cs));
                    }
                    const int b = wbase + mt * 16 + half * 8 + g8;
                    __stcg((float2*)&d_h[wbuf][b][u0 + 2 * ql],
                           make_float2(hv[0], hv[1]));
                }
            }
        }

        grid_bar((unsigned)(t + 1) * NBLK);
    }

    // ---- tail: out[b][o] = h_final[b] . Wout[o] + bout[o]; h_final in buf 0
    {
        const int gtid = blk * NTHR + tid;          // 0..32767 == BATCH*OUTD
        const int b = gtid & 63, o = gtid >> 6;
        const float4* hr = (const float4*)&d_h[0][b][0];
        const float4* wr = (const float4*)(Wout + ((size_t)o << 10));
        float s = __ldg(&bout[o]);
#pragma unroll 4
        for (int k = 0; k < HID / 4; k++) {
            float4 h4 = __ldcg(hr + k);
            float4 w4 = __ldg(wr + k);
            s += h4.x * w4.x + h4.y * w4.y + h4.z * w4.z + h4.w * w4.w;
        }
        out[(size_t)b * OUTD + o] = s;
    }
}

// ============================================================================
extern "C" void kernel_launch(void* const* d_in, const int* in_sizes, int n_in,
                              void* d_out, int out_size)
{
    (void)in_sizes; (void)n_in; (void)out_size;
    const float* x    = (const float*)d_in[0];
    const float* Wxf  = (const float*)d_in[1];
    const float* Whf  = (const float*)d_in[2];
    const float* bhf  = (const float*)d_in[3];
    const float* Wxi  = (const float*)d_in[4];
    const float* Whi  = (const float*)d_in[5];
    const float* bhi  = (const float*)d_in[6];
    const float* Wxc  = (const float*)d_in[7];
    const float* Whc  = (const float*)d_in[8];
    const float* bhc  = (const float*)d_in[9];
    const float* Wxo  = (const float*)d_in[10];
    const float* Who  = (const float*)d_in[11];
    const float* bho  = (const float*)d_in[12];
    const float* Wout = (const float*)d_in[13];
    const float* bout = (const float*)d_in[14];
    float* out = (float*)d_out;

    static bool attr_set = false;
    if (!attr_set) {
        cudaFuncSetAttribute(lstm_kernel,
                             cudaFuncAttributeMaxDynamicSharedMemorySize, SMEM_TOTAL);
        attr_set = true;
    }

    prep_kernel<<<2048, 256>>>(x, Wxf, Whf, bhf, Wxi, Whi, bhi,
                               Wxc, Whc, bhc, Wxo, Who, bho);
    lstm_kernel<<<NBLK, NTHR, SMEM_TOTAL>>>(Wout, bout, out);
}

// round 6
// speedup vs baseline: 7.0181x; 2.3438x over previous
#include <cuda_runtime.h>
#include <cstdint>

// Problem constants
#define BATCH 64
#define SEQT  512
#define IN    512
#define HID   1024
#define G4    4096
#define KTOT  1536
#define OUTD  512

#define NBLK  128           // persistent grid, 1 CTA/SM
#define NTHR  256           // 8 warps, ALL compute (split-K x split-N)
#define K8TOT 192           // k8 steps total (KTOT/8)
#define K8X   64            // k8 steps in x region
#define KSL   48            // k8 steps per warp K-slice (192/4)

// smem: W fragment-packed (resident) + 8 partial tiles
#define WF_FLOATS (K8TOT * 4 * 32 * 2)     // 49152 floats = 196608 B
#define P_PITCH   17
#define P_TILE    (64 * P_PITCH)           // 1088 floats per warp tile
#define SMEM_TOTAL ((WF_FLOATS + 8 * P_TILE) * 4)   // 231424 B

// ---- device-global scratch ----
__device__ float    d_W[(size_t)G4 * KTOT];              // tf32-rounded, packed cols
__device__ float    d_bias[G4];
__device__ float    d_xfrag[(size_t)SEQT * K8X * 4 * 32 * 4]; // x in mma-fragment order
__device__ float    d_hfrag[2 * 128 * 4 * 32 * 4];      // h in fragment order, dbl-buf
__device__ float    d_hfin[BATCH * HID];                 // final h, linear
__device__ unsigned d_bar;

// ============================ helpers =======================================
__device__ __forceinline__ float tf32r(float v) {
    uint32_t r;
    asm("cvt.rna.tf32.f32 %0, %1;" : "=r"(r) : "f"(v));
    return __uint_as_float(r);
}
__device__ __forceinline__ void mma_tf32(float c[4], const uint32_t a[4],
                                         const uint32_t b[2]) {
    asm volatile(
        "mma.sync.aligned.m16n8k8.row.col.f32.tf32.tf32.f32 "
        "{%0,%1,%2,%3}, {%4,%5,%6,%7}, {%8,%9}, {%0,%1,%2,%3};"
        : "+f"(c[0]), "+f"(c[1]), "+f"(c[2]), "+f"(c[3])
        : "r"(a[0]), "r"(a[1]), "r"(a[2]), "r"(a[3]), "r"(b[0]), "r"(b[1]));
}
__device__ __forceinline__ float sigf(float v)     { return 1.f / (1.f + __expf(-v)); }
__device__ __forceinline__ float tanhfast(float v) { return 2.f / (1.f + __expf(-2.f * v)) - 1.f; }

// ============================ prep kernel ===================================
// Packed W column j (global 0..4095): gate g=(j>>3)&3 (f,i,c,o), unit=(j>>5)*8+(j&7).
// x pre-packed into A-fragment order: [t][k8][mt][lane][reg], reg mapping:
//   b = mt*16 + (lane>>2) + 8*(reg&1),  k = k8*8 + (lane&3) + 4*(reg>>1)
__global__ void prep_kernel(
    const float* __restrict__ x,
    const float* __restrict__ Wxf, const float* __restrict__ Whf, const float* __restrict__ bhf,
    const float* __restrict__ Wxi, const float* __restrict__ Whi, const float* __restrict__ bhi,
    const float* __restrict__ Wxc, const float* __restrict__ Whc, const float* __restrict__ bhc,
    const float* __restrict__ Wxo, const float* __restrict__ Who, const float* __restrict__ bho)
{
    const float* Wx[4] = {Wxf, Wxi, Wxc, Wxo};
    const float* Wh[4] = {Whf, Whi, Whc, Who};
    const float* bh[4] = {bhf, bhi, bhc, bho};

    size_t gid = (size_t)blockIdx.x * blockDim.x + threadIdx.x;
    size_t str = (size_t)gridDim.x * blockDim.x;

    for (size_t i = gid; i < (size_t)G4 * KTOT; i += str) {
        int j = (int)(i / KTOT), k = (int)(i % KTOT);
        int g = (j >> 3) & 3;
        int r = (j >> 5) * 8 + (j & 7);
        float v = (k < IN) ? Wx[g][(size_t)r * IN + k]
                           : Wh[g][(size_t)r * HID + (k - IN)];
        d_W[i] = tf32r(v);
    }
    for (size_t i = gid; i < (size_t)G4; i += str) {
        int g = (int)((i >> 3) & 3);
        int r = (int)((i >> 5) * 8 + (i & 7));
        d_bias[i] = bh[g][r];
    }
    // x fragments
    for (size_t i = gid; i < (size_t)SEQT * K8X * 4 * 32 * 4; i += str) {
        int r    = (int)(i & 3);
        int lane = (int)((i >> 2) & 31);
        int mt   = (int)((i >> 7) & 3);
        int k8   = (int)((i >> 9) & 63);
        int t    = (int)(i >> 15);
        int b = mt * 16 + (lane >> 2) + 8 * (r & 1);
        int k = k8 * 8 + (lane & 3) + 4 * (r >> 1);
        d_xfrag[i] = tf32r(x[((size_t)b * SEQT + t) * IN + k]);
    }
    for (size_t i = gid; i < (size_t)2 * 128 * 4 * 32 * 4; i += str)
        d_hfrag[i] = 0.f;
    if (gid == 0) d_bar = 0u;
}

// ============================ grid barrier ==================================
__device__ __forceinline__ void grid_bar(unsigned target)
{
    __syncthreads();
    if (threadIdx.x == 0) {
        __threadfence();
        atomicAdd(&d_bar, 1u);
        while (*(volatile unsigned*)&d_bar < target) __nanosleep(32);
        __threadfence();
    }
    __syncthreads();
}

// A-fragment load: one LDG.128, coalesced across the warp
__device__ __forceinline__ uint4 ldA(int t, int rbuf, int k8, int mt, int lane)
{
    if (k8 < K8X) {
        size_t off = ((((size_t)t * K8X + k8) * 4 + mt) * 32 + lane) * 4;
        return __ldg((const uint4*)&d_xfrag[off]);
    } else {
        size_t off = (((size_t)(rbuf * 128 + (k8 - K8X)) * 4 + mt) * 32 + lane) * 4;
        return __ldcg((const uint4*)&d_hfrag[off]);
    }
}

// ============================ main persistent kernel ========================
__global__ void __launch_bounds__(NTHR, 1) lstm_kernel(
    const float* __restrict__ Wout,
    const float* __restrict__ bout,
    float* __restrict__ out)
{
    extern __shared__ float smf[];
    float* Wf = smf;                 // fragment-packed weights
    float* P  = smf + WF_FLOATS;     // 8 partial tiles [w][64][P_PITCH]

    const int tid  = threadIdx.x;
    const int wid  = tid >> 5;
    const int lane = tid & 31;
    const int g8   = lane >> 2;
    const int ql   = lane & 3;
    const int blk  = blockIdx.x;

    const int kslice = wid >> 1;          // 0..3
    const int nhalf  = wid & 1;           // 0..1
    const int k8base = kslice * KSL;

    // ---- one-time: pack this CTA's W columns into fragment order ----
    // Wf[(k8*4+nt)*64 + lane*2 + {0,1}]: b0=W[n][k8*8+ql], b1=W[n][k8*8+ql+4],
    // n = blk*32 + nt*8 + g8
    for (int j = tid; j < K8TOT * 4 * 32; j += NTHR) {
        int k8 = j >> 7, nt = (j >> 5) & 3, ln = j & 31;
        size_t col = (size_t)(blk * 32 + nt * 8 + (ln >> 2));
        int k = k8 * 8 + (ln & 3);
        Wf[j * 2 + 0] = __ldg(&d_W[col * KTOT + k]);
        Wf[j * 2 + 1] = __ldg(&d_W[col * KTOT + k + 4]);
    }
    __syncthreads();

    // ---- epilogue persistent state: thread owns (b,u) pairs p and p+256 ----
    const int b0p = tid >> 3,          u0p = tid & 7;
    const int b1p = (tid + 256) >> 3,  u1p = (tid + 256) & 7;
    float cst0 = 0.f, cst1 = 0.f;
    float bias0[4], bias1[4];
#pragma unroll
    for (int g = 0; g < 4; g++) {
        bias0[g] = __ldg(&d_bias[blk * 32 + g * 8 + u0p]);
        bias1[g] = __ldg(&d_bias[blk * 32 + g * 8 + u1p]);
    }

    for (int t = 0; t < SEQT; t++) {
        const int rbuf = t & 1, wbuf = rbuf ^ 1;

        // -------- MMA phase: no intra-CTA syncs --------
        float acc[4][2][4];
#pragma unroll
        for (int mt = 0; mt < 4; mt++)
#pragma unroll
            for (int n2 = 0; n2 < 2; n2++)
#pragma unroll
                for (int c = 0; c < 4; c++) acc[mt][n2][c] = 0.f;

        uint4 apf[3][4];
#pragma unroll
        for (int d = 0; d < 3; d++)
#pragma unroll
            for (int mt = 0; mt < 4; mt++)
                apf[d][mt] = ldA(t, rbuf, k8base + d, mt, lane);

#pragma unroll 3
        for (int j = 0; j < KSL; j++) {
            const int slot = j % 3;
            uint32_t bfr[2][2];
#pragma unroll
            for (int n2 = 0; n2 < 2; n2++) {
                float2 bv = *(const float2*)
                    &Wf[(((k8base + j) * 4) + nhalf * 2 + n2) * 64 + lane * 2];
                bfr[n2][0] = __float_as_uint(bv.x);
                bfr[n2][1] = __float_as_uint(bv.y);
            }
#pragma unroll
            for (int mt = 0; mt < 4; mt++)
#pragma unroll
                for (int n2 = 0; n2 < 2; n2++)
                    mma_tf32(acc[mt][n2], (const uint32_t*)&apf[slot][mt], bfr[n2]);
            if (j + 3 < KSL) {
#pragma unroll
                for (int mt = 0; mt < 4; mt++)
                    apf[slot][mt] = ldA(t, rbuf, k8base + j + 3, mt, lane);
            }
        }

        // -------- write partials --------
        float* Pw = P + wid * P_TILE;
#pragma unroll
        for (int mt = 0; mt < 4; mt++)
#pragma unroll
            for (int n2 = 0; n2 < 2; n2++)
#pragma unroll
                for (int c = 0; c < 4; c++) {
                    int row = mt * 16 + g8 + 8 * (c >> 1);
                    int col = n2 * 8 + 2 * ql + (c & 1);
                    Pw[row * P_PITCH + col] = acc[mt][n2][c];
                }
        __syncthreads();

        // -------- reduction + gate fusion (2 pairs per thread) --------
        {
            // pair 0
            float pa[4];
#pragma unroll
            for (int g = 0; g < 4; g++) {
                int col16 = (g & 1) * 8 + u0p;
                int wh = g >> 1;
                float s = bias0[g];
#pragma unroll
                for (int ks = 0; ks < 4; ks++)
                    s += P[(ks * 2 + wh) * P_TILE + b0p * P_PITCH + col16];
                pa[g] = s;
            }
            float f = sigf(pa[0]), ig = sigf(pa[1]);
            float ch = tanhfast(pa[2]), o = sigf(pa[3]);
            cst0 = f * cst0 + ig * ch;
            float hv = tf32r(o * tanhfast(cst0));
            int ug = blk * 8 + u0p;
            if (t < SEQT - 1) {
                int hidx = ug >> 3;
                int mtw  = b0p >> 4;
                int lw   = (b0p & 7) * 4 + (ug & 3);
                int rw   = 2 * ((ug >> 2) & 1) + ((b0p >> 3) & 1);
                __stcg(&d_hfrag[(((size_t)(wbuf * 128 + hidx) * 4 + mtw) * 32 + lw) * 4 + rw], hv);
            } else {
                d_hfin[b0p * HID + ug] = hv;
            }
        }
        {
            // pair 1
            float pa[4];
#pragma unroll
            for (int g = 0; g < 4; g++) {
                int col16 = (g & 1) * 8 + u1p;
                int wh = g >> 1;
                float s = bias1[g];
#pragma unroll
                for (int ks = 0; ks < 4; ks++)
                    s += P[(ks * 2 + wh) * P_TILE + b1p * P_PITCH + col16];
                pa[g] = s;
            }
            float f = sigf(pa[0]), ig = sigf(pa[1]);
            float ch = tanhfast(pa[2]), o = sigf(pa[3]);
            cst1 = f * cst1 + ig * ch;
            float hv = tf32r(o * tanhfast(cst1));
            int ug = blk * 8 + u1p;
            if (t < SEQT - 1) {
                int hidx = ug >> 3;
                int mtw  = b1p >> 4;
                int lw   = (b1p & 7) * 4 + (ug & 3);
                int rw   = 2 * ((ug >> 2) & 1) + ((b1p >> 3) & 1);
                __stcg(&d_hfrag[(((size_t)(wbuf * 128 + hidx) * 4 + mtw) * 32 + lw) * 4 + rw], hv);
            } else {
                d_hfin[b1p * HID + ug] = hv;
            }
        }

        grid_bar((unsigned)(t + 1) * NBLK);
    }

    // ---- tail: out[b][o] = h_final[b] . Wout[o] + bout[o]
    {
        const int gtid = blk * NTHR + tid;          // 0..32767 == BATCH*OUTD
        const int b = gtid & 63, o = gtid >> 6;
        const float4* hr = (const float4*)&d_hfin[(size_t)b * HID];
        const float4* wr = (const float4*)(Wout + ((size_t)o << 10));
        float s = __ldg(&bout[o]);
#pragma unroll 4
        for (int k = 0; k < HID / 4; k++) {
            float4 h4 = __ldcg(hr + k);
            float4 w4 = __ldg(wr + k);
            s += h4.x * w4.x + h4.y * w4.y + h4.z * w4.z + h4.w * w4.w;
        }
        out[(size_t)b * OUTD + o] = s;
    }
}

// ============================================================================
extern "C" void kernel_launch(void* const* d_in, const int* in_sizes, int n_in,
                              void* d_out, int out_size)
{
    (void)in_sizes; (void)n_in; (void)out_size;
    const float* x    = (const float*)d_in[0];
    const float* Wxf  = (const float*)d_in[1];
    const float* Whf  = (const float*)d_in[2];
    const float* bhf  = (const float*)d_in[3];
    const float* Wxi  = (const float*)d_in[4];
    const float* Whi  = (const float*)d_in[5];
    const float* bhi  = (const float*)d_in[6];
    const float* Wxc  = (const float*)d_in[7];
    const float* Whc  = (const float*)d_in[8];
    const float* bhc  = (const float*)d_in[9];
    const float* Wxo  = (const float*)d_in[10];
    const float* Who  = (const float*)d_in[11];
    const float* bho  = (const float*)d_in[12];
    const float* Wout = (const float*)d_in[13];
    const float* bout = (const float*)d_in[14];
    float* out = (float*)d_out;

    cudaFuncSetAttribute(lstm_kernel,
                         cudaFuncAttributeMaxDynamicSharedMemorySize, SMEM_TOTAL);

    prep_kernel<<<2048, 256>>>(x, Wxf, Whf, bhf, Wxi, Whi, bhi,
                               Wxc, Whc, bhc, Wxo, Who, bho);
    lstm_kernel<<<NBLK, NTHR, SMEM_TOTAL>>>(Wout, bout, out);
}

// round 7
// speedup vs baseline: 7.2671x; 1.0355x over previous
#include <cuda_runtime.h>
#include <cstdint>

// Problem constants
#define BATCH 64
#define SEQT  512
#define IN    512
#define HID   1024
#define G4    4096
#define KTOT  1536
#define OUTD  512

#define NBLK  128           // persistent grid, 1 CTA/SM
#define NTHR  256           // 8 warps = (kslice 0..3) x (mhalf 0..1)
#define K8TOT 192           // k8 steps total (KTOT/8)
#define K8X   64            // k8 steps in x region
#define KSL   48            // k8 steps per warp K-slice (192/4)

// smem: W fragment-packed (resident) + 8 partial tiles (32x32, pitch 33)
#define WF_FLOATS (K8TOT * 4 * 32 * 2)     // 49152 floats = 196608 B
#define P_PITCH   33
#define P_TILE    (32 * P_PITCH)           // 1056 floats per warp tile
#define SMEM_TOTAL ((WF_FLOATS + 8 * P_TILE) * 4)   // 230400 B

// ---- device-global scratch ----
__device__ float    d_W[(size_t)G4 * KTOT];              // tf32-rounded, packed cols
__device__ float    d_bias[G4];
__device__ float    d_xfrag[(size_t)SEQT * K8X * 4 * 32 * 4]; // x in mma-fragment order
__device__ float    d_hfrag[2 * 128 * 4 * 32 * 4];      // h in fragment order, dbl-buf
__device__ float    d_hfin[BATCH * HID];                 // final h, linear
__device__ unsigned d_bar;

// ============================ helpers =======================================
__device__ __forceinline__ float tf32r(float v) {
    uint32_t r;
    asm("cvt.rna.tf32.f32 %0, %1;" : "=r"(r) : "f"(v));
    return __uint_as_float(r);
}
__device__ __forceinline__ void mma_tf32(float c[4], const uint32_t a[4],
                                         const uint32_t b[2]) {
    asm volatile(
        "mma.sync.aligned.m16n8k8.row.col.f32.tf32.tf32.f32 "
        "{%0,%1,%2,%3}, {%4,%5,%6,%7}, {%8,%9}, {%0,%1,%2,%3};"
        : "+f"(c[0]), "+f"(c[1]), "+f"(c[2]), "+f"(c[3])
        : "r"(a[0]), "r"(a[1]), "r"(a[2]), "r"(a[3]), "r"(b[0]), "r"(b[1]));
}
__device__ __forceinline__ float sigf(float v)     { return 1.f / (1.f + __expf(-v)); }
__device__ __forceinline__ float tanhfast(float v) { return 2.f / (1.f + __expf(-2.f * v)) - 1.f; }

// ============================ prep kernel ===================================
// Packed W column j (global 0..4095): gate g=(j>>3)&3 (f,i,c,o), unit=(j>>5)*8+(j&7).
// x pre-packed into A-fragment order: [t][k8][mt][lane][reg], reg mapping:
//   b = mt*16 + (lane>>2) + 8*(reg&1),  k = k8*8 + (lane&3) + 4*(reg>>1)
__global__ void prep_kernel(
    const float* __restrict__ x,
    const float* __restrict__ Wxf, const float* __restrict__ Whf, const float* __restrict__ bhf,
    const float* __restrict__ Wxi, const float* __restrict__ Whi, const float* __restrict__ bhi,
    const float* __restrict__ Wxc, const float* __restrict__ Whc, const float* __restrict__ bhc,
    const float* __restrict__ Wxo, const float* __restrict__ Who, const float* __restrict__ bho)
{
    const float* Wx[4] = {Wxf, Wxi, Wxc, Wxo};
    const float* Wh[4] = {Whf, Whi, Whc, Who};
    const float* bh[4] = {bhf, bhi, bhc, bho};

    size_t gid = (size_t)blockIdx.x * blockDim.x + threadIdx.x;
    size_t str = (size_t)gridDim.x * blockDim.x;

    for (size_t i = gid; i < (size_t)G4 * KTOT; i += str) {
        int j = (int)(i / KTOT), k = (int)(i % KTOT);
        int g = (j >> 3) & 3;
        int r = (j >> 5) * 8 + (j & 7);
        float v = (k < IN) ? Wx[g][(size_t)r * IN + k]
                           : Wh[g][(size_t)r * HID + (k - IN)];
        d_W[i] = tf32r(v);
    }
    for (size_t i = gid; i < (size_t)G4; i += str) {
        int g = (int)((i >> 3) & 3);
        int r = (int)((i >> 5) * 8 + (i & 7));
        d_bias[i] = bh[g][r];
    }
    // x fragments
    for (size_t i = gid; i < (size_t)SEQT * K8X * 4 * 32 * 4; i += str) {
        int r    = (int)(i & 3);
        int lane = (int)((i >> 2) & 31);
        int mt   = (int)((i >> 7) & 3);
        int k8   = (int)((i >> 9) & 63);
        int t    = (int)(i >> 15);
        int b = mt * 16 + (lane >> 2) + 8 * (r & 1);
        int k = k8 * 8 + (lane & 3) + 4 * (r >> 1);
        d_xfrag[i] = tf32r(x[((size_t)b * SEQT + t) * IN + k]);
    }
    for (size_t i = gid; i < (size_t)2 * 128 * 4 * 32 * 4; i += str)
        d_hfrag[i] = 0.f;
    if (gid == 0) d_bar = 0u;
}

// ============================ grid barrier ==================================
__device__ __forceinline__ void grid_bar(unsigned target)
{
    __syncthreads();
    if (threadIdx.x == 0) {
        __threadfence();
        atomicAdd(&d_bar, 1u);
        while (*(volatile unsigned*)&d_bar < target) __nanosleep(32);
        __threadfence();
    }
    __syncthreads();
}

// A-fragment load: one LDG.128, coalesced across the warp
__device__ __forceinline__ uint4 ldA(int t, int rbuf, int k8, int mt, int lane)
{
    if (k8 < K8X) {
        size_t off = ((((size_t)t * K8X + k8) * 4 + mt) * 32 + lane) * 4;
        return __ldg((const uint4*)&d_xfrag[off]);
    } else {
        size_t off = (((size_t)(rbuf * 128 + (k8 - K8X)) * 4 + mt) * 32 + lane) * 4;
        return __ldcg((const uint4*)&d_hfrag[off]);
    }
}

// ============================ main persistent kernel ========================
__global__ void __launch_bounds__(NTHR, 1) lstm_kernel(
    const float* __restrict__ Wout,
    const float* __restrict__ bout,
    float* __restrict__ out)
{
    extern __shared__ float smf[];
    float* Wf = smf;                 // fragment-packed weights
    float* P  = smf + WF_FLOATS;     // 8 partial tiles [w][32][P_PITCH]

    const int tid  = threadIdx.x;
    const int wid  = tid >> 5;
    const int lane = tid & 31;
    const int g8   = lane >> 2;
    const int ql   = lane & 3;
    const int blk  = blockIdx.x;

    const int kslice = wid >> 1;          // 0..3
    const int mhalf  = wid & 1;           // 0..1 (batch half)
    const int k8base = kslice * KSL;
    const int mbase  = mhalf * 2;         // mt in {mbase, mbase+1}

    // ---- one-time: pack this CTA's W columns into fragment order ----
    // Wf[(k8*4+nt)*64 + lane*2 + {0,1}]: b0=W[n][k8*8+ql], b1=W[n][k8*8+ql+4],
    // n = blk*32 + nt*8 + g8
    for (int j = tid; j < K8TOT * 4 * 32; j += NTHR) {
        int k8 = j >> 7, nt = (j >> 5) & 3, ln = j & 31;
        size_t col = (size_t)(blk * 32 + nt * 8 + (ln >> 2));
        int k = k8 * 8 + (ln & 3);
        Wf[j * 2 + 0] = __ldg(&d_W[col * KTOT + k]);
        Wf[j * 2 + 1] = __ldg(&d_W[col * KTOT + k + 4]);
    }
    __syncthreads();

    // ---- epilogue persistent state: thread owns (b,u) pairs p and p+256 ----
    const int b0p = tid >> 3,          u0p = tid & 7;
    const int b1p = (tid + 256) >> 3,  u1p = (tid + 256) & 7;
    float cst0 = 0.f, cst1 = 0.f;
    float bias0[4], bias1[4];
#pragma unroll
    for (int g = 0; g < 4; g++) {
        bias0[g] = __ldg(&d_bias[blk * 32 + g * 8 + u0p]);
        bias1[g] = __ldg(&d_bias[blk * 32 + g * 8 + u1p]);
    }

    for (int t = 0; t < SEQT; t++) {
        const int rbuf = t & 1, wbuf = rbuf ^ 1;

        // -------- MMA phase: M=32 (batch half) x N=32, K=384, no syncs -----
        float acc[2][4][4];
#pragma unroll
        for (int m2 = 0; m2 < 2; m2++)
#pragma unroll
            for (int nt = 0; nt < 4; nt++)
#pragma unroll
                for (int c = 0; c < 4; c++) acc[m2][nt][c] = 0.f;

        uint4 apf[3][2];
#pragma unroll
        for (int d = 0; d < 3; d++)
#pragma unroll
            for (int m2 = 0; m2 < 2; m2++)
                apf[d][m2] = ldA(t, rbuf, k8base + d, mbase + m2, lane);

#pragma unroll 3
        for (int j = 0; j < KSL; j++) {
            const int slot = j % 3;
            uint32_t bfr[4][2];
#pragma unroll
            for (int nt = 0; nt < 4; nt++) {
                float2 bv = *(const float2*)
                    &Wf[(((k8base + j) * 4) + nt) * 64 + lane * 2];
                bfr[nt][0] = __float_as_uint(bv.x);
                bfr[nt][1] = __float_as_uint(bv.y);
            }
#pragma unroll
            for (int m2 = 0; m2 < 2; m2++)
#pragma unroll
                for (int nt = 0; nt < 4; nt++)
                    mma_tf32(acc[m2][nt], (const uint32_t*)&apf[slot][m2], bfr[nt]);
            if (j + 3 < KSL) {
#pragma unroll
                for (int m2 = 0; m2 < 2; m2++)
                    apf[slot][m2] = ldA(t, rbuf, k8base + j + 3, mbase + m2, lane);
            }
        }

        // -------- write partials (rows are local batch 0..31 of this half) --
        float* Pw = P + wid * P_TILE;
#pragma unroll
        for (int m2 = 0; m2 < 2; m2++)
#pragma unroll
            for (int nt = 0; nt < 4; nt++)
#pragma unroll
                for (int c = 0; c < 4; c++) {
                    int row = m2 * 16 + g8 + 8 * (c >> 1);
                    int col = nt * 8 + 2 * ql + (c & 1);
                    Pw[row * P_PITCH + col] = acc[m2][nt][c];
                }
        __syncthreads();

        // -------- reduction + gate fusion (2 pairs per thread) --------
        {
            // pair 0: batch b0p, unit u0p
            const int mh = b0p >> 5, r = b0p & 31;
            float pa[4];
#pragma unroll
            for (int g = 0; g < 4; g++) {
                float s = bias0[g];
#pragma unroll
                for (int ks = 0; ks < 4; ks++)
                    s += P[(ks * 2 + mh) * P_TILE + r * P_PITCH + g * 8 + u0p];
                pa[g] = s;
            }
            float f = sigf(pa[0]), ig = sigf(pa[1]);
            float ch = tanhfast(pa[2]), o = sigf(pa[3]);
            cst0 = f * cst0 + ig * ch;
            float hv = tf32r(o * tanhfast(cst0));
            int ug = blk * 8 + u0p;
            if (t < SEQT - 1) {
                int hidx = ug >> 3;
                int mtw  = b0p >> 4;
                int lw   = (b0p & 7) * 4 + (ug & 3);
                int rw   = 2 * ((ug >> 2) & 1) + ((b0p >> 3) & 1);
                __stcg(&d_hfrag[(((size_t)(wbuf * 128 + hidx) * 4 + mtw) * 32 + lw) * 4 + rw], hv);
            } else {
                d_hfin[b0p * HID + ug] = hv;
            }
        }
        {
            // pair 1: batch b1p, unit u1p
            const int mh = b1p >> 5, r = b1p & 31;
            float pa[4];
#pragma unroll
            for (int g = 0; g < 4; g++) {
                float s = bias1[g];
#pragma unroll
                for (int ks = 0; ks < 4; ks++)
                    s += P[(ks * 2 + mh) * P_TILE + r * P_PITCH + g * 8 + u1p];
                pa[g] = s;
            }
            float f = sigf(pa[0]), ig = sigf(pa[1]);
            float ch = tanhfast(pa[2]), o = sigf(pa[3]);
            cst1 = f * cst1 + ig * ch;
            float hv = tf32r(o * tanhfast(cst1));
            int ug = blk * 8 + u1p;
            if (t < SEQT - 1) {
                int hidx = ug >> 3;
                int mtw  = b1p >> 4;
                int lw   = (b1p & 7) * 4 + (ug & 3);
                int rw   = 2 * ((ug >> 2) & 1) + ((b1p >> 3) & 1);
                __stcg(&d_hfrag[(((size_t)(wbuf * 128 + hidx) * 4 + mtw) * 32 + lw) * 4 + rw], hv);
            } else {
                d_hfin[b1p * HID + ug] = hv;
            }
        }

        grid_bar((unsigned)(t + 1) * NBLK);
    }

    // ---- tail: out[b][o] = h_final[b] . Wout[o] + bout[o]
    {
        const int gtid = blk * NTHR + tid;          // 0..32767 == BATCH*OUTD
        const int b = gtid & 63, o = gtid >> 6;
        const float4* hr = (const float4*)&d_hfin[(size_t)b * HID];
        const float4* wr = (const float4*)(Wout + ((size_t)o << 10));
        float s = __ldg(&bout[o]);
#pragma unroll 4
        for (int k = 0; k < HID / 4; k++) {
            float4 h4 = __ldcg(hr + k);
            float4 w4 = __ldg(wr + k);
            s += h4.x * w4.x + h4.y * w4.y + h4.z * w4.z + h4.w * w4.w;
        }
        out[(size_t)b * OUTD + o] = s;
    }
}

// ============================================================================
extern "C" void kernel_launch(void* const* d_in, const int* in_sizes, int n_in,
                              void* d_out, int out_size)
{
    (void)in_sizes; (void)n_in; (void)out_size;
    const float* x    = (const float*)d_in[0];
    const float* Wxf  = (const float*)d_in[1];
    const float* Whf  = (const float*)d_in[2];
    const float* bhf  = (const float*)d_in[3];
    const float* Wxi  = (const float*)d_in[4];
    const float* Whi  = (const float*)d_in[5];
    const float* bhi  = (const float*)d_in[6];
    const float* Wxc  = (const float*)d_in[7];
    const float* Whc  = (const float*)d_in[8];
    const float* bhc  = (const float*)d_in[9];
    const float* Wxo  = (const float*)d_in[10];
    const float* Who  = (const float*)d_in[11];
    const float* bho  = (const float*)d_in[12];
    const float* Wout = (const float*)d_in[13];
    const float* bout = (const float*)d_in[14];
    float* out = (float*)d_out;

    cudaFuncSetAttribute(lstm_kernel,
                         cudaFuncAttributeMaxDynamicSharedMemorySize, SMEM_TOTAL);

    prep_kernel<<<2048, 256>>>(x, Wxf, Whf, bhf, Wxi, Whi, bhi,
                               Wxc, Whc, bhc, Wxo, Who, bho);
    lstm_kernel<<<NBLK, NTHR, SMEM_TOTAL>>>(Wout, bout, out);
}